// round 14
// baseline (speedup 1.0000x reference)
#include <cuda_runtime.h>
#include <math.h>

// out[b,c,h,w] = prod_{p=1..24} cos(x_p + w_p), 5x5 'same' window.
// cos(x+w_p) = cos(w_p) * (cos x - tan(w_p) sin x)
// => out = scale * prod_{p>=1} fmaf(-tan w_p, sin x, cos x), scale = prod cos w_p.
// Block = HALF plane (32 rows x 64 cols), 128 threads, grid 1024 (~1% tail).
// Out-of-plane halo cells are constant (cos,sin)=(1,0): no loads.
// Real rows loaded as back-to-back float4 (MLP>=4), sincos to smem.
// Main: thread owns column j + 16-row segment, walks 20 tile rows with
// explicit next-row prefetch; per row computes 5 weight-row variants H_di,
// multiplies into pending output i=r-di; retires one output per row.
// Weights in __constant__ -> uniform-register FFMA operands (no GPR tax);
// prep writes directly into the constant backing store (2-node graph).
// __launch_bounds__(128,7): 7*148=1036 >= 1024 single wave, 71-reg budget
// gives ptxas room to schedule the prefetch (R12's 62-reg cap was too tight).

#define HW    64
#define PLANE (HW * HW)
#define TW    68   // 64 + 2*2 col halo
#define TR    36   // 32 + 2*2 row halo

__constant__ float c_w[26];   // [p]= -tan(w_p) (p=1..24), [25]= prod cos

__global__ void prep_kernel(const float* __restrict__ w, float* __restrict__ cw_store)
{
    __shared__ float cwsh[25];
    const int p = threadIdx.x;
    if (p < 25) {
        float s, c;
        sincosf(w[p], &s, &c);      // accurate; only 25 values
        cw_store[p] = -s / c;
        cwsh[p] = c;
    }
    __syncwarp();
    if (p == 0) {
        float sc = 1.0f;
#pragma unroll
        for (int q = 1; q < 25; ++q) sc *= cwsh[q];
        cw_store[25] = sc;
    }
}

__global__ __launch_bounds__(128, 7)
void quanv_kernel(const float* __restrict__ x,
                  float* __restrict__ out)
{
    __shared__ float2 scs[TR][TW];   // (cos x, sin x); halo -> (1,0)

    const int blk   = blockIdx.x;
    const int plane = blk >> 1;
    const int hb    = blk & 1;            // 0 = top half, 1 = bottom half
    const int base  = hb * 32;            // first output row
    const float* xp = x + (size_t)plane * PLANE;
    float* op = out + (size_t)plane * PLANE;
    const int tid = threadIdx.x;

    // ---- Constant halo fill (272 cells):
    // 2 out-of-plane edge rows (full 68 cols) + 4 halo cols over the 34 real rows.
    const int e0 = hb ? 34 : 0;   // edge tile rows e0, e0+1
    const int s0 = hb ? 0 : 2;    // first real tile row (34 of them)
    for (int h = tid; h < 272; h += 128) {
        int r, c;
        if (h < 136) {                    // 2 edge rows x 68
            r = e0 + (h / TW);
            c = h - (h / TW) * TW;
        } else {                          // 34 rows x cols {0,1,66,67}
            int q = h - 136;              // 0..135
            r = s0 + (q >> 2);
            int cc = q & 3;
            c = (cc < 2) ? cc : (64 + cc);
        }
        scs[r][c] = make_float2(1.0f, 0.0f);
    }

    // ---- Interior: 34 real rows (global band gb..gb+33) x 16 float4 = 544.
    // 4 full passes + 1 predicated, all LDGs issued back-to-back (MLP).
    const int gb = hb ? 30 : 0;           // first global row of the band
    const int t0 = s0;                    // tile row of band row 0
    float4 xv[5];
#pragma unroll
    for (int k = 0; k < 4; ++k) {
        const int q = tid + 128 * k;      // 0..511
        xv[k] = *reinterpret_cast<const float4*>(xp + (gb + (q >> 4)) * HW + ((q & 15) << 2));
    }
    if (tid < 32) {                       // band rows 32,33
        const int q = 512 + tid;
        xv[4] = *reinterpret_cast<const float4*>(xp + (gb + (q >> 4)) * HW + ((q & 15) << 2));
    }
#pragma unroll
    for (int k = 0; k < 5; ++k) {
        const int q = tid + 128 * k;
        if (k == 4 && tid >= 32) break;
        const int row = t0 + (q >> 4);    // tile row
        const int col = ((q & 15) << 2) + 2;
        float s, c;
        __sincosf(xv[k].x, &s, &c); scs[row][col + 0] = make_float2(c, s);
        __sincosf(xv[k].y, &s, &c); scs[row][col + 1] = make_float2(c, s);
        __sincosf(xv[k].z, &s, &c); scs[row][col + 2] = make_float2(c, s);
        __sincosf(xv[k].w, &s, &c); scs[row][col + 3] = make_float2(c, s);
    }
    __syncthreads();

    const float scale = c_w[25];

    // ---- Main: thread = (column j, 16-row segment). Walk 20 tile rows;
    // at walk index r, variant di feeds pending output i = r - di.
    // Software pipeline: row r+1's loads issued before row r's math.
    const int j  = tid & 63;          // 0..63
    const int i0 = (tid >> 6) * 16;   // 0 or 16 (relative to base)

    float acc[16];

    float2 n0 = scs[i0][j + 0];
    float2 n1 = scs[i0][j + 1];
    float2 n2 = scs[i0][j + 2];
    float2 n3 = scs[i0][j + 3];
    float2 n4 = scs[i0][j + 4];

#pragma unroll
    for (int r = 0; r < 20; ++r) {
        const float2 v0 = n0, v1 = n1, v2 = n2, v3 = n3, v4 = n4;
        if (r < 19) {
            const int tr = i0 + r + 1;
            n0 = scs[tr][j + 0];
            n1 = scs[tr][j + 1];
            n2 = scs[tr][j + 2];
            n3 = scs[tr][j + 3];
            n4 = scs[tr][j + 4];
        }

#pragma unroll
        for (int di = 0; di < 5; ++di) {
            const int i = r - di;                  // output index in segment
            if (i < 0 || i >= 16) continue;
            float h;
            if (di == 0) {
                // p = 0 (Z_0 wire) excluded: dj = 1..4 only.
                h = (fmaf(c_w[1], v1.y, v1.x) * fmaf(c_w[2], v2.y, v2.x))
                  * (fmaf(c_w[3], v3.y, v3.x) * fmaf(c_w[4], v4.y, v4.x));
            } else {
                const int b = di * 5;
                h = (fmaf(c_w[b    ], v0.y, v0.x) * fmaf(c_w[b + 1], v1.y, v1.x))
                  * (fmaf(c_w[b + 2], v2.y, v2.x) * fmaf(c_w[b + 3], v3.y, v3.x));
                h *= fmaf(c_w[b + 4], v4.y, v4.x);
            }
            acc[i] = (di == 0) ? h : acc[i] * h;
            if (di == 4)   // output complete -> store, free the register
                op[(base + i0 + i) * HW + j] = acc[i] * scale;
        }
    }
}

extern "C" void kernel_launch(void* const* d_in, const int* in_sizes, int n_in,
                              void* d_out, int out_size)
{
    const float* x = (const float*)d_in[0];
    const float* w = (const float*)d_in[1];
    float* out = (float*)d_out;

    const int planes = in_sizes[0] / PLANE;   // B*C = 512

    // Device pointer to the __constant__ backing store (no allocation).
    void* cw_ptr = nullptr;
    cudaGetSymbolAddress(&cw_ptr, c_w);

    prep_kernel<<<1, 32>>>(w, (float*)cw_ptr);
    quanv_kernel<<<planes * 2, 128>>>(x, out);
}